// round 14
// baseline (speedup 1.0000x reference)
#include <cuda_runtime.h>
#include <cuda_fp16.h>

#define HWSZ (512*512)
#define HALO (42*42)
typedef unsigned long long u64;

__device__ __forceinline__ float ex2f(float x) {
    float r; asm("ex2.approx.f32 %0, %1;" : "=f"(r) : "f"(x)); return r;
}
__device__ __forceinline__ float rcpf(float x) {
    float r; asm("rcp.approx.f32 %0, %1;" : "=f"(r) : "f"(x)); return r;
}
__device__ __forceinline__ u64 pk(float a, float b) {
    u64 r; asm("mov.b64 %0, {%1,%2};" : "=l"(r) : "f"(a), "f"(b)); return r;
}
__device__ __forceinline__ u64 add2(u64 a, u64 b) {
    u64 r; asm("add.rn.f32x2 %0, %1, %2;" : "=l"(r) : "l"(a), "l"(b)); return r;
}
__device__ __forceinline__ unsigned int h2u(__half2 h) {
    return *reinterpret_cast<unsigned int*>(&h);
}
__device__ __forceinline__ __half2 u2h(unsigned int u) {
    return *reinterpret_cast<__half2*>(&u);
}

// Tile 32x32 outputs, block (32,4)=128 thr, 8 output rows/thread.
// Site = 16 B (one uint4, one LDS.128):
//   .x = (c0,c1) fp16x2   .y = (c2, 1.0) fp16x2
//   .z = (u, u4) fp16x2   .w = (u9, u16) fp16x2
// Taps in HFMA2; per-(s,o) fp16 chunk promoted to f32x2 once per site-row.
// launch_bounds(128,7): 7 blocks/SM -> n_conc = 1036 >= grid 1024 -> ONE wave.
__global__ __launch_bounds__(128, 7) void GaussPSF_kernel(
    const float* __restrict__ img,
    const float* __restrict__ psf,
    float* __restrict__ out)
{
    __shared__ uint4 tile[HALO + 1];      // +1 pad: unconditional prefetch

    const int tx = threadIdx.x;           // 0..31
    const int ty = threadIdx.y;           // 0..3
    const int tid = ty * 32 + tx;
    const int x0 = blockIdx.x * 32;
    const int y0 = blockIdx.y * 32;
    const int b  = blockIdx.z;

    const float* imb = img + (size_t)b * 3 * HWSZ;
    const float* psb = psf + (size_t)b * HWSZ;

    // ---- stage halo: EX2/RCP + power chain once per site; pack fp16 ----
    for (int i = tid; i < HALO; i += 128) {
        int sy = i / 42;
        int sx = i - sy * 42;
        int gy = y0 - 5 + sy;
        int gx = x0 - 5 + sx;
        uint4 r;
        if ((unsigned)gy < 512u && (unsigned)gx < 512u) {
            int p = gy * 512 + gx;
            float c0 = imb[p];
            float c1 = imb[HWSZ + p];
            float c2 = imb[2 * HWSZ + p];
            float w = psb[p];
            float t  = fmaf(w + w, w, 1e-5f);
            float u  = ex2f(-1.4426950408889634f * rcpf(t));
            float u2 = u * u;
            float u4 = u2 * u2;
            float u8 = u4 * u4;
            r.x = h2u(__floats2half2_rn(c0, c1));
            r.y = h2u(__floats2half2_rn(c2, 1.0f));
            r.z = h2u(__floats2half2_rn(u,  u4));
            r.w = h2u(__floats2half2_rn(u8 * u, u8 * u8));  // u9, u16
        } else {
            r.x = 0u; r.y = 0u; r.z = 0u; r.w = 0u;          // mask
        }
        tile[i] = r;
    }
    __syncthreads();

    // ---- 8 outputs per thread: rows y0 + ty*8 + (0..7), column x0 + tx ----
    u64 a01[8], a2w[8];                   // f32x2 master accumulators
    #pragma unroll
    for (int o = 0; o < 8; ++o) { a01[o] = 0ull; a2w[o] = 0ull; }

    const int rowbase = ty * 8;
    const __half2 hz = u2h(0u);

    #pragma unroll
    for (int s = 0; s < 18; ++s) {
        const int base = (rowbase + s) * 42 + tx;
        uint4 bv = tile[base];            // prefetch j=0

        // per-row fp16 chunk accumulators (reset each s; DCE for inactive o)
        __half2 h01[8], h2w[8];
        #pragma unroll
        for (int o = 0; o < 8; ++o) { h01[o] = hz; h2w[o] = hz; }

        #pragma unroll
        for (int j = 0; j < 11; ++j) {
            uint4 nv = tile[base + j + 1];    // unconditional prefetch

            __half2 c01 = u2h(bv.x);
            __half2 c2w = u2h(bv.y);
            __half2 uv  = u2h(bv.z);
            __half2 u916 = u2h(bv.w);

            __half2 D[6];
            D[1] = __low2half2(uv);           // {u,u}
            D[2] = __high2half2(uv);          // {u4,u4}
            D[3] = __low2half2(u916);         // {u9,u9}
            D[4] = __high2half2(u916);        // {u16,u16}
            D[5] = __hmul2(D[3], D[4]);       // {u25,u25}

            const int dxa = (j < 5) ? (5 - j) : (j - 5);
            __half2 m01 = (dxa == 0) ? c01 : __hmul2(c01, D[dxa]);
            __half2 m2w = (dxa == 0) ? c2w : __hmul2(c2w, D[dxa]);

            #pragma unroll
            for (int o = 0; o < 8; ++o) {
                const int dy  = s - 5 - o;     // compile-time after unroll
                const int dya = (dy < 0) ? -dy : dy;
                if (dya <= 5) {
                    if (dya == 0) {
                        h01[o] = __hadd2(h01[o], m01);
                        h2w[o] = __hadd2(h2w[o], m2w);
                    } else {
                        h01[o] = __hfma2(m01, D[dya], h01[o]);
                        h2w[o] = __hfma2(m2w, D[dya], h2w[o]);
                    }
                }
            }
            bv = nv;
        }

        // promote this row's chunks into f32x2 accumulators
        #pragma unroll
        for (int o = 0; o < 8; ++o) {
            const int dy  = s - 5 - o;
            const int dya = (dy < 0) ? -dy : dy;
            if (dya <= 5) {
                float2 f1 = __half22float2(h01[o]);
                float2 f2 = __half22float2(h2w[o]);
                a01[o] = add2(a01[o], pk(f1.x, f1.y));
                a2w[o] = add2(a2w[o], pk(f2.x, f2.y));
            }
        }
    }

    // ---- normalize & write ----
    float* ob = out + (size_t)b * 3 * HWSZ;
    #pragma unroll
    for (int o = 0; o < 8; ++o) {
        float o0, o1, o2, ws;
        asm("mov.b64 {%0,%1}, %2;" : "=f"(o0), "=f"(o1) : "l"(a01[o]));
        asm("mov.b64 {%0,%1}, %2;" : "=f"(o2), "=f"(ws) : "l"(a2w[o]));
        float rw = rcpf(ws);
        int y = y0 + rowbase + o;
        int p = y * 512 + x0 + tx;
        ob[p]            = o0 * rw;
        ob[HWSZ + p]     = o1 * rw;
        ob[2 * HWSZ + p] = o2 * rw;
    }
}

extern "C" void kernel_launch(void* const* d_in, const int* in_sizes, int n_in,
                              void* d_out, int out_size)
{
    const float* img = (const float*)d_in[0];   // (4,3,512,512) f32
    const float* psf = (const float*)d_in[1];   // (4,512,512)   f32
    float* out = (float*)d_out;                 // (4,3,512,512) f32

    dim3 block(32, 4, 1);
    dim3 grid(512 / 32, 512 / 32, 4);
    GaussPSF_kernel<<<grid, block>>>(img, psf, out);
}

// round 15
// speedup vs baseline: 1.0801x; 1.0801x over previous
#include <cuda_runtime.h>
#include <cuda_fp16.h>

#define HWSZ (512*512)
#define HALO (42*42)
typedef unsigned long long u64;

__device__ __forceinline__ float ex2f(float x) {
    float r; asm("ex2.approx.f32 %0, %1;" : "=f"(r) : "f"(x)); return r;
}
__device__ __forceinline__ float rcpf(float x) {
    float r; asm("rcp.approx.f32 %0, %1;" : "=f"(r) : "f"(x)); return r;
}
__device__ __forceinline__ u64 pk(float a, float b) {
    u64 r; asm("mov.b64 %0, {%1,%2};" : "=l"(r) : "f"(a), "f"(b)); return r;
}
__device__ __forceinline__ u64 add2(u64 a, u64 b) {
    u64 r; asm("add.rn.f32x2 %0, %1, %2;" : "=l"(r) : "l"(a), "l"(b)); return r;
}
__device__ __forceinline__ unsigned int h2u(__half2 h) {
    return *reinterpret_cast<unsigned int*>(&h);
}
__device__ __forceinline__ __half2 u2h(unsigned int u) {
    return *reinterpret_cast<__half2*>(&u);
}

// Tile 32x32 outputs, block (32,4)=128 thr, 8 output rows/thread.
// Site = 16 B (one uint4, one LDS.128):
//   .x = (c0,c1) fp16x2   .y = (c2, 1.0) fp16x2
//   .z = (u, u4) fp16x2   .w = (u9, u16) fp16x2
// Taps in HFMA2. fp16 chunks now span TWO site-rows before promotion to the
// f32x2 master accumulators (promote when (s-o) in {1,3,5,7,9,10}) -> 48
// promote events/thread instead of 88 (-16% of issue slots incl. f32 add2s).
__global__ __launch_bounds__(128, 7) void GaussPSF_kernel(
    const float* __restrict__ img,
    const float* __restrict__ psf,
    float* __restrict__ out)
{
    __shared__ uint4 tile[HALO + 1];      // +1 pad: unconditional prefetch

    const int tx = threadIdx.x;           // 0..31
    const int ty = threadIdx.y;           // 0..3
    const int tid = ty * 32 + tx;
    const int x0 = blockIdx.x * 32;
    const int y0 = blockIdx.y * 32;
    const int b  = blockIdx.z;

    const float* imb = img + (size_t)b * 3 * HWSZ;
    const float* psb = psf + (size_t)b * HWSZ;

    // ---- stage halo: EX2/RCP + power chain once per site; pack fp16 ----
    for (int i = tid; i < HALO; i += 128) {
        int sy = i / 42;
        int sx = i - sy * 42;
        int gy = y0 - 5 + sy;
        int gx = x0 - 5 + sx;
        uint4 r;
        if ((unsigned)gy < 512u && (unsigned)gx < 512u) {
            int p = gy * 512 + gx;
            float c0 = imb[p];
            float c1 = imb[HWSZ + p];
            float c2 = imb[2 * HWSZ + p];
            float w = psb[p];
            float t  = fmaf(w + w, w, 1e-5f);
            float u  = ex2f(-1.4426950408889634f * rcpf(t));
            float u2 = u * u;
            float u4 = u2 * u2;
            float u8 = u4 * u4;
            r.x = h2u(__floats2half2_rn(c0, c1));
            r.y = h2u(__floats2half2_rn(c2, 1.0f));
            r.z = h2u(__floats2half2_rn(u,  u4));
            r.w = h2u(__floats2half2_rn(u8 * u, u8 * u8));  // u9, u16
        } else {
            r.x = 0u; r.y = 0u; r.z = 0u; r.w = 0u;          // mask
        }
        tile[i] = r;
    }
    __syncthreads();

    // ---- 8 outputs per thread: rows y0 + ty*8 + (0..7), column x0 + tx ----
    u64 a01[8], a2w[8];                   // f32x2 master accumulators
    __half2 h01[8], h2w[8];               // fp16 chunk accumulators
    const __half2 hz = u2h(0u);
    #pragma unroll
    for (int o = 0; o < 8; ++o) {
        a01[o] = 0ull; a2w[o] = 0ull;
        h01[o] = hz;   h2w[o] = hz;
    }

    const int rowbase = ty * 8;

    #pragma unroll
    for (int s = 0; s < 18; ++s) {
        const int base = (rowbase + s) * 42 + tx;
        uint4 bv = tile[base];            // prefetch j=0

        #pragma unroll
        for (int j = 0; j < 11; ++j) {
            uint4 nv = tile[base + j + 1];    // unconditional prefetch

            __half2 c01 = u2h(bv.x);
            __half2 c2w = u2h(bv.y);
            __half2 uv  = u2h(bv.z);
            __half2 u916 = u2h(bv.w);

            __half2 D[6];
            D[1] = __low2half2(uv);           // {u,u}
            D[2] = __high2half2(uv);          // {u4,u4}
            D[3] = __low2half2(u916);         // {u9,u9}
            D[4] = __high2half2(u916);        // {u16,u16}
            D[5] = __hmul2(D[3], D[4]);       // {u25,u25}

            const int dxa = (j < 5) ? (5 - j) : (j - 5);
            __half2 m01 = (dxa == 0) ? c01 : __hmul2(c01, D[dxa]);
            __half2 m2w = (dxa == 0) ? c2w : __hmul2(c2w, D[dxa]);

            #pragma unroll
            for (int o = 0; o < 8; ++o) {
                const int dy  = s - 5 - o;     // compile-time after unroll
                const int dya = (dy < 0) ? -dy : dy;
                if (dya <= 5) {
                    if (dya == 0) {
                        h01[o] = __hadd2(h01[o], m01);
                        h2w[o] = __hadd2(h2w[o], m2w);
                    } else {
                        h01[o] = __hfma2(m01, D[dya], h01[o]);
                        h2w[o] = __hfma2(m2w, D[dya], h2w[o]);
                    }
                }
            }
            bv = nv;
        }

        // promote chunks spanning two site-rows: r = s-o in {1,3,5,7,9,10}
        #pragma unroll
        for (int o = 0; o < 8; ++o) {
            const int r = s - o;               // compile-time
            if (r >= 0 && r <= 10 && (((r & 1) == 1) || r == 10)) {
                float2 f1 = __half22float2(h01[o]);
                float2 f2 = __half22float2(h2w[o]);
                a01[o] = add2(a01[o], pk(f1.x, f1.y));
                a2w[o] = add2(a2w[o], pk(f2.x, f2.y));
                h01[o] = hz;
                h2w[o] = hz;
            }
        }
    }

    // ---- normalize & write ----
    float* ob = out + (size_t)b * 3 * HWSZ;
    #pragma unroll
    for (int o = 0; o < 8; ++o) {
        float o0, o1, o2, ws;
        asm("mov.b64 {%0,%1}, %2;" : "=f"(o0), "=f"(o1) : "l"(a01[o]));
        asm("mov.b64 {%0,%1}, %2;" : "=f"(o2), "=f"(ws) : "l"(a2w[o]));
        float rw = rcpf(ws);
        int y = y0 + rowbase + o;
        int p = y * 512 + x0 + tx;
        ob[p]            = o0 * rw;
        ob[HWSZ + p]     = o1 * rw;
        ob[2 * HWSZ + p] = o2 * rw;
    }
}

extern "C" void kernel_launch(void* const* d_in, const int* in_sizes, int n_in,
                              void* d_out, int out_size)
{
    const float* img = (const float*)d_in[0];   // (4,3,512,512) f32
    const float* psf = (const float*)d_in[1];   // (4,512,512)   f32
    float* out = (float*)d_out;                 // (4,3,512,512) f32

    dim3 block(32, 4, 1);
    dim3 grid(512 / 32, 512 / 32, 4);
    GaussPSF_kernel<<<grid, block>>>(img, psf, out);
}